// round 7
// baseline (speedup 1.0000x reference)
#include <cuda_runtime.h>
#include <cuda_fp16.h>
#include <math.h>
#include <stdint.h>

#define NMAX 100000
#define EMAX 1600000
#define DD 64
#define SCB 200          // persistent blocks; 200*512 = 102400 >= NMAX
#define EPB 8000         // edges per block  (200*8000 = 1.6M >= EMAX)

// ---------------- device scratch (no allocations allowed) ----------------
__device__ int    g_counts[NMAX];        // zeroed in-kernel after use
__device__ int    g_fill[NMAX];
__device__ int    g_rowptr[NMAX + 1];
__device__ int    g_esrc[EMAX];          // BYTE offsets: src * 128
__device__ int    g_bsum[SCB];
__device__ unsigned long long g_barctr;  // monotonic, never reset (replay-safe)
__device__ __half g_yh[(size_t)NMAX * DD];
__device__ float  g_agg[(size_t)NMAX * DD];
__device__ float  g_M1[DD * DD];
__device__ float  g_M2[DD * DD];
__device__ float  g_v[DD];
__device__ float  g_bias;

// monotonic all-block barrier for exactly SCB co-resident blocks
__device__ __forceinline__ void grid_barrier() {
    __syncthreads();
    if (threadIdx.x == 0) {
        __threadfence();
        unsigned long long my = atomicAdd(&g_barctr, 1ULL) + 1ULL;
        unsigned long long target = ((my + SCB - 1) / SCB) * (unsigned long long)SCB;
        while (atomicAdd(&g_barctr, 0ULL) < target) { }
        __threadfence();
    }
    __syncthreads();
}

// ---------------- persistent preprocessing ---------------------------------
// Phase A: local dtype detect; histogram of dst (stashed in SMEM); matprep.
// Phase B: 3-phase scan of counts -> rowptr/fill (+ zero counts).
// Phase C: scatter src (as byte offsets) using SMEM dst stash.
__global__ void __launch_bounds__(256)
pre_kernel(const void* __restrict__ edges,
           const float* __restrict__ Wp,
           const float* __restrict__ Wt,
           const float* __restrict__ Wout,
           const float* __restrict__ bout,
           int N, int E) {
    __shared__ int sdst[EPB];
    __shared__ int sm[256];
    __shared__ int sb[256];
    __shared__ int s_is64;
    int b = blockIdx.x, t = threadIdx.x;

    // ---- local dtype detect (hot 8KB region, every block, no barrier) ----
    if (t < 64) {
        const int* w = (const int*)edges;
        int local = 0;
        for (int i = t; i < 2048; i += 64)
            if (w[2 * i + 1] != 0) local = 1;
        // warp-level OR then one thread writes
        for (int off = 16; off; off >>= 1)
            local |= __shfl_xor_sync(0xffffffffu, local, off);
        if (t == 0) s_is64 = 0;             // placeholder, set below
        if (t == 0) s_is64 = 0;
        if (t == 0) s_is64 = (local ? 0 : 1) * 0;   // overwritten below
        if (t == 0) s_is64 = local ? 0 : 1;
    }
    __syncthreads();
    int is64 = s_is64;

    // ---- Phase A: histogram + smem dst stash ----
    int e0 = b * EPB;
    int e1 = e0 + EPB; if (e1 > E) e1 = E;
    int cnt_local = e1 - e0;
    if (is64) {
        const long long* p = (const long long*)edges;
        for (int i = t; i < cnt_local; i += 256) {
            int dst = (int)p[(size_t)E + e0 + i];
            sdst[i] = dst;
            atomicAdd(&g_counts[dst], 1);
        }
    } else {
        const int* p = (const int*)edges;
        for (int i = t; i < cnt_local; i += 256) {
            int dst = p[E + e0 + i];
            sdst[i] = dst;
            atomicAdd(&g_counts[dst], 1);
        }
    }

    // ---- matprep on blocks 0..15 (4096 lanes), overlapped with Phase A ----
    if (b < 16) {
        int id = b * 256 + t;
        int i = id >> 6, k = id & 63;
        float s1 = 0.f, s2 = 0.f;
#pragma unroll
        for (int m = 0; m < DD; m++) {
            s1 += Wp[1 * DD * DD + i * DD + m] * Wt[0 * DD * DD + m * DD + k];
            s2 += Wp[2 * DD * DD + i * DD + m] * Wt[1 * DD * DD + m * DD + k];
        }
        g_M1[id] = s1;
        g_M2[id] = s2;
        if (i == 0) {
            float sv = 0.f;
#pragma unroll
            for (int m = 0; m < DD; m++)
                sv += Wout[m] * Wt[2 * DD * DD + m * DD + k];
            g_v[k] = sv;
        }
        if (id == 0) g_bias = bout[0];
    }

    grid_barrier();

    // ---- Phase B: scan counts over this block's 512-node chunk ----
    int base = b * 512 + t * 2;
    int c0 = (base < N) ? g_counts[base] : 0;
    int c1 = (base + 1 < N) ? g_counts[base + 1] : 0;
    int s = c0 + c1;
    sm[t] = s;
    __syncthreads();
    for (int off = 128; off; off >>= 1) {
        if (t < off) sm[t] += sm[t + off];
        __syncthreads();
    }
    if (t == 0) g_bsum[b] = sm[0];

    grid_barrier();

    // block offset = exclusive prefix of g_bsum
    sb[t] = (t < SCB) ? g_bsum[t] : 0;
    __syncthreads();
    for (int off = 1; off < 256; off <<= 1) {
        int v = (t >= off) ? sb[t - off] : 0;
        __syncthreads();
        sb[t] += v;
        __syncthreads();
    }
    int blockoff = (b == 0) ? 0 : sb[b - 1];
    if (b == SCB - 1 && t == 0) g_rowptr[N] = sb[SCB - 1];

    // local exclusive scan + write + zero counts
    sm[t] = s;
    __syncthreads();
    for (int off = 1; off < 256; off <<= 1) {
        int v = (t >= off) ? sm[t - off] : 0;
        __syncthreads();
        sm[t] += v;
        __syncthreads();
    }
    int pre = sm[t] - s + blockoff;
    if (base < N)     { g_rowptr[base] = pre;          g_fill[base] = pre;          g_counts[base] = 0; }
    if (base + 1 < N) { g_rowptr[base + 1] = pre + c0; g_fill[base + 1] = pre + c0; g_counts[base + 1] = 0; }

    grid_barrier();

    // ---- Phase C: scatter (src from gmem coalesced, dst from smem) ----
    if (is64) {
        const long long* p = (const long long*)edges;
        for (int i = t; i < cnt_local; i += 256) {
            int src = (int)p[e0 + i];
            int pos = atomicAdd(&g_fill[sdst[i]], 1);
            g_esrc[pos] = src << 7;
        }
    } else {
        const int* p = (const int*)edges;
        for (int i = t; i < cnt_local; i += 256) {
            int src = p[e0 + i];
            int pos = atomicAdd(&g_fill[sdst[i]], 1);
            g_esrc[pos] = src << 7;
        }
    }
}

// ---------------- GEMM: yh[64-row tile] = half( in @ M^T ) ---------------
__global__ void gemm_kernel(const float* __restrict__ x,
                            const float* __restrict__ M,
                            __half* __restrict__ out, int N) {
    __shared__ float sx[DD][DD + 1];
    __shared__ float sM[DD][DD + 1];
    int t = threadIdx.x;
    int base = blockIdx.x * DD;

#pragma unroll
    for (int i = 0; i < 4; i++) {
        int v = t + 256 * i;
        int r = v >> 4;
        int c4 = (v & 15) * 4;
        float4 mv = *(const float4*)&M[r * DD + c4];
        sM[r][c4] = mv.x; sM[r][c4 + 1] = mv.y; sM[r][c4 + 2] = mv.z; sM[r][c4 + 3] = mv.w;
        float4 xv = make_float4(0.f, 0.f, 0.f, 0.f);
        if (base + r < N)
            xv = *(const float4*)&x[(size_t)(base + r) * DD + c4];
        sx[r][c4] = xv.x; sx[r][c4 + 1] = xv.y; sx[r][c4 + 2] = xv.z; sx[r][c4 + 3] = xv.w;
    }
    __syncthreads();

    int tc = (t & 15) * 4;
    int tr = (t >> 4) * 4;
    float acc[4][4];
#pragma unroll
    for (int i = 0; i < 4; i++)
#pragma unroll
        for (int j = 0; j < 4; j++) acc[i][j] = 0.f;

#pragma unroll 16
    for (int k = 0; k < DD; k++) {
        float a0 = sx[tr][k], a1 = sx[tr + 1][k], a2 = sx[tr + 2][k], a3 = sx[tr + 3][k];
        float b0 = sM[tc][k], b1 = sM[tc + 1][k], b2 = sM[tc + 2][k], b3 = sM[tc + 3][k];
        acc[0][0] += a0 * b0; acc[0][1] += a0 * b1; acc[0][2] += a0 * b2; acc[0][3] += a0 * b3;
        acc[1][0] += a1 * b0; acc[1][1] += a1 * b1; acc[1][2] += a1 * b2; acc[1][3] += a1 * b3;
        acc[2][0] += a2 * b0; acc[2][1] += a2 * b1; acc[2][2] += a2 * b2; acc[2][3] += a2 * b3;
        acc[3][0] += a3 * b0; acc[3][1] += a3 * b1; acc[3][2] += a3 * b2; acc[3][3] += a3 * b3;
    }

#pragma unroll
    for (int i = 0; i < 4; i++) {
        int row = base + tr + i;
        if (row < N) {
            __half2 h0 = __floats2half2_rn(acc[i][0], acc[i][1]);
            __half2 h1 = __floats2half2_rn(acc[i][2], acc[i][3]);
            uint2 pack;
            pack.x = *(const unsigned*)&h0;
            pack.y = *(const unsigned*)&h1;
            *(uint2*)&out[(size_t)row * DD + tc] = pack;
        }
    }
}

// ---------------- aggregation core (fp16 gather, uniform-ldg indices) -----
__device__ __forceinline__ void agg_core_h(const __half* __restrict__ yh,
                                           int beg, int end, int lane,
                                           __half2& m01, __half2& m23) {
    const __half2 ninf = __float2half2_rn(-INFINITY);
    m01 = ninf; m23 = ninf;
    const char* Y = (const char*)yh;
    int half_id = lane >> 4;
    int qb = (lane & 15) * 8;
    int p = beg;
    for (; p + 8 <= end; p += 8) {         // 4 edges per half-warp
        int o0 = __ldg(&g_esrc[p     + half_id]);
        int o1 = __ldg(&g_esrc[p + 2 + half_id]);
        int o2 = __ldg(&g_esrc[p + 4 + half_id]);
        int o3 = __ldg(&g_esrc[p + 6 + half_id]);
        uint2 a = *(const uint2*)(Y + o0 + qb);
        uint2 c = *(const uint2*)(Y + o1 + qb);
        uint2 d = *(const uint2*)(Y + o2 + qb);
        uint2 e = *(const uint2*)(Y + o3 + qb);
        m01 = __hmax2(m01, __hmax2(__hmax2(*(__half2*)&a.x, *(__half2*)&c.x),
                                   __hmax2(*(__half2*)&d.x, *(__half2*)&e.x)));
        m23 = __hmax2(m23, __hmax2(__hmax2(*(__half2*)&a.y, *(__half2*)&c.y),
                                   __hmax2(*(__half2*)&d.y, *(__half2*)&e.y)));
    }
    if (p + 4 <= end) {                    // 2 edges per half-warp
        int o0 = __ldg(&g_esrc[p     + half_id]);
        int o1 = __ldg(&g_esrc[p + 2 + half_id]);
        uint2 a = *(const uint2*)(Y + o0 + qb);
        uint2 c = *(const uint2*)(Y + o1 + qb);
        m01 = __hmax2(m01, __hmax2(*(__half2*)&a.x, *(__half2*)&c.x));
        m23 = __hmax2(m23, __hmax2(*(__half2*)&a.y, *(__half2*)&c.y));
        p += 4;
    }
    for (; p < end; p++) {                 // tail: both halves duplicate
        int o = __ldg(&g_esrc[p]);
        uint2 a = *(const uint2*)(Y + o + qb);
        m01 = __hmax2(m01, *(__half2*)&a.x);
        m23 = __hmax2(m23, *(__half2*)&a.y);
    }
    unsigned u01 = *(unsigned*)&m01, u23 = *(unsigned*)&m23;
    unsigned o01 = __shfl_xor_sync(0xffffffffu, u01, 16);
    unsigned o23 = __shfl_xor_sync(0xffffffffu, u23, 16);
    m01 = __hmax2(m01, *(__half2*)&o01);
    m23 = __hmax2(m23, *(__half2*)&o23);
}

// agg[i] = max_{src} yh[src] - yh[i]  (0 for isolated nodes)
__global__ void agg_kernel(const __half* __restrict__ yh,
                           float* __restrict__ out, int N) {
    int wid = (blockIdx.x * blockDim.x + threadIdx.x) >> 5;
    int lane = threadIdx.x & 31;
    if (wid >= N) return;
    int beg = g_rowptr[wid];
    int end = g_rowptr[wid + 1];
    __half2 m01, m23;
    agg_core_h(yh, beg, end, lane, m01, m23);
    if (lane < 16) {
        int q = lane;
        float4 o;
        if (beg == end) {
            o = make_float4(0.f, 0.f, 0.f, 0.f);
        } else {
            uint2 sp = *(const uint2*)&yh[(size_t)wid * DD + q * 4];
            float2 f01 = __half22float2(m01);
            float2 f23 = __half22float2(m23);
            float2 s01 = __half22float2(*(__half2*)&sp.x);
            float2 s23 = __half22float2(*(__half2*)&sp.y);
            o.x = f01.x - s01.x; o.y = f01.y - s01.y;
            o.z = f23.x - s23.x; o.w = f23.y - s23.y;
        }
        *(float4*)&out[(size_t)wid * DD + q * 4] = o;
    }
}

// last layer: agg + dot with folded head vector + sigmoid, fused.
__global__ void agg_final_kernel(const __half* __restrict__ yh,
                                 float* __restrict__ out, int N) {
    int wid = (blockIdx.x * blockDim.x + threadIdx.x) >> 5;
    int lane = threadIdx.x & 31;
    if (wid >= N) return;
    int beg = g_rowptr[wid];
    int end = g_rowptr[wid + 1];
    __half2 m01, m23;
    agg_core_h(yh, beg, end, lane, m01, m23);
    int q = lane & 15;
    float p = 0.f;
    if (beg != end) {
        uint2 sp = *(const uint2*)&yh[(size_t)wid * DD + q * 4];
        float2 f01 = __half22float2(m01);
        float2 f23 = __half22float2(m23);
        float2 s01 = __half22float2(*(__half2*)&sp.x);
        float2 s23 = __half22float2(*(__half2*)&sp.y);
        float4 vv = *(const float4*)&g_v[q * 4];
        p = (f01.x - s01.x) * vv.x + (f01.y - s01.y) * vv.y
          + (f23.x - s23.x) * vv.z + (f23.y - s23.y) * vv.w;
    }
#pragma unroll
    for (int off = 8; off; off >>= 1)
        p += __shfl_xor_sync(0xffffffffu, p, off);
    if (lane == 0)
        out[wid] = 1.f / (1.f + expf(-(p + g_bias)));
}

extern "C" void kernel_launch(void* const* d_in, const int* in_sizes, int n_in,
                              void* d_out, int out_size) {
    const float* x     = (const float*)d_in[0];
    const void*  edges = d_in[1];
    const float* Wp    = (const float*)d_in[2];
    const float* Wt    = (const float*)d_in[3];
    const float* Wout  = (const float*)d_in[4];
    const float* bout  = (const float*)d_in[5];
    float* out = (float*)d_out;

    int N = in_sizes[0] / DD;
    int E = in_sizes[1] / 2;

    __half* yhp;
    float *aggp, *m1p, *m2p;
    cudaGetSymbolAddress((void**)&yhp, g_yh);
    cudaGetSymbolAddress((void**)&aggp, g_agg);
    cudaGetSymbolAddress((void**)&m1p, g_M1);
    cudaGetSymbolAddress((void**)&m2p, g_M2);

    const int TB = 256;
    int wbl = ((N * 32) + TB - 1) / TB;   // warp-per-node grids
    int gbl = (N + DD - 1) / DD;          // 64-row GEMM tiles

    pre_kernel<<<SCB, 256>>>(edges, Wp, Wt, Wout, bout, N, E);

    // layer 0
    gemm_kernel<<<gbl, 256>>>(x, Wp, yhp, N);
    agg_kernel<<<wbl, TB>>>(yhp, aggp, N);
    // layer 1
    gemm_kernel<<<gbl, 256>>>(aggp, m1p, yhp, N);
    agg_kernel<<<wbl, TB>>>(yhp, aggp, N);
    // layer 2 + head
    gemm_kernel<<<gbl, 256>>>(aggp, m2p, yhp, N);
    agg_final_kernel<<<wbl, TB>>>(yhp, out, N);
}

// round 8
// speedup vs baseline: 1.2634x; 1.2634x over previous
#include <cuda_runtime.h>
#include <cuda_fp16.h>
#include <math.h>
#include <stdint.h>

#define NMAX 100000
#define EMAX 1600000
#define DD 64
#define SCB 200          // scan blocks; 200*512 = 102400 >= NMAX; co-resident

// ---------------- device scratch (no allocations allowed) ----------------
__device__ int    g_counts[NMAX];        // zeroed by scan_fused after use
__device__ int    g_fill[NMAX];
__device__ int    g_rowptr[NMAX + 1];
__device__ int    g_esrc[EMAX];          // BYTE offsets: src * 128
__device__ int    g_bsum[SCB];
__device__ unsigned long long g_barctr;  // monotonic, never reset (replay-safe)
__device__ __half g_yh[(size_t)NMAX * DD];
__device__ float  g_agg[(size_t)NMAX * DD];
__device__ float  g_M1[DD * DD];
__device__ float  g_M2[DD * DD];
__device__ float  g_v[DD];
__device__ float  g_bias;
__device__ int    g_is64;

// ---------------- dtype detection for edges (int64 vs int32) -------------
__global__ void detect_kernel(const void* __restrict__ edges) {
    __shared__ int nz;
    if (threadIdx.x == 0) nz = 0;
    __syncthreads();
    const int* w = (const int*)edges;
    int local = 0;
    for (int i = threadIdx.x; i < 2048; i += blockDim.x)
        if (w[2 * i + 1] != 0) local = 1;
    if (local) atomicOr(&nz, 1);
    __syncthreads();
    if (threadIdx.x == 0) g_is64 = (nz == 0) ? 1 : 0;
}

__global__ void hist_kernel(const void* __restrict__ edges, int E) {
    int e = blockIdx.x * blockDim.x + threadIdx.x;
    if (e >= E) return;
    int dst;
    if (g_is64) dst = (int)((const long long*)edges)[E + e];
    else        dst = ((const int*)edges)[E + e];
    atomicAdd(&g_counts[dst], 1);
}

// ---------------- fused: matprep + single-kernel scan ---------------------
__device__ __forceinline__ void grid_barrier_200() {
    __syncthreads();
    if (threadIdx.x == 0) {
        __threadfence();
        unsigned long long my = atomicAdd(&g_barctr, 1ULL) + 1ULL;
        unsigned long long target = ((my + SCB - 1) / SCB) * (unsigned long long)SCB;
        while (atomicAdd(&g_barctr, 0ULL) < target) { }
        __threadfence();
    }
    __syncthreads();
}

__global__ void scan_fused(const float* __restrict__ Wp,
                           const float* __restrict__ Wt,
                           const float* __restrict__ Wout,
                           const float* __restrict__ bout, int N) {
    int b = blockIdx.x, t = threadIdx.x;

    // ---- matprep on blocks 0..15 (4096 lanes) ----
    if (b < 16) {
        int id = b * 256 + t;
        int i = id >> 6, k = id & 63;
        float s1 = 0.f, s2 = 0.f;
#pragma unroll
        for (int m = 0; m < DD; m++) {
            s1 += Wp[1 * DD * DD + i * DD + m] * Wt[0 * DD * DD + m * DD + k];
            s2 += Wp[2 * DD * DD + i * DD + m] * Wt[1 * DD * DD + m * DD + k];
        }
        g_M1[id] = s1;
        g_M2[id] = s2;
        if (i == 0) {
            float sv = 0.f;
#pragma unroll
            for (int m = 0; m < DD; m++)
                sv += Wout[m] * Wt[2 * DD * DD + m * DD + k];
            g_v[k] = sv;
        }
        if (id == 0) g_bias = bout[0];
    }

    // ---- phase 1: block sum over its 512-element chunk ----
    __shared__ int sm[256];
    int base = b * 512 + t * 2;
    int c0 = (base < N) ? g_counts[base] : 0;
    int c1 = (base + 1 < N) ? g_counts[base + 1] : 0;
    int s = c0 + c1;
    sm[t] = s;
    __syncthreads();
    for (int off = 128; off; off >>= 1) {
        if (t < off) sm[t] += sm[t + off];
        __syncthreads();
    }
    if (t == 0) g_bsum[b] = sm[0];

    grid_barrier_200();

    // ---- phase 2a: block offset = exclusive prefix of g_bsum ----
    __shared__ int sb[256];
    sb[t] = (t < SCB) ? g_bsum[t] : 0;
    __syncthreads();
    for (int off = 1; off < 256; off <<= 1) {
        int v = (t >= off) ? sb[t - off] : 0;
        __syncthreads();
        sb[t] += v;
        __syncthreads();
    }
    int blockoff = (b == 0) ? 0 : sb[b - 1];
    if (b == SCB - 1 && t == 0) g_rowptr[N] = sb[SCB - 1];

    // ---- phase 2b: local exclusive scan + write + zero counts ----
    sm[t] = s;
    __syncthreads();
    for (int off = 1; off < 256; off <<= 1) {
        int v = (t >= off) ? sm[t - off] : 0;
        __syncthreads();
        sm[t] += v;
        __syncthreads();
    }
    int pre = sm[t] - s + blockoff;
    if (base < N)     { g_rowptr[base] = pre;          g_fill[base] = pre;          g_counts[base] = 0; }
    if (base + 1 < N) { g_rowptr[base + 1] = pre + c0; g_fill[base + 1] = pre + c0; g_counts[base + 1] = 0; }
}

__global__ void scatter_kernel(const void* __restrict__ edges, int E) {
    int e = blockIdx.x * blockDim.x + threadIdx.x;
    if (e >= E) return;
    int src, dst;
    if (g_is64) {
        const long long* p = (const long long*)edges;
        src = (int)p[e]; dst = (int)p[E + e];
    } else {
        const int* p = (const int*)edges;
        src = p[e]; dst = p[E + e];
    }
    int pos = atomicAdd(&g_fill[dst], 1);
    g_esrc[pos] = src << 7;              // byte offset into fp16 rows (64*2B)
}

// ---------------- GEMM: yh = half( in @ M^T ), LDS.128 inner loop --------
// 256 threads, 64x64 tile, 4x4 micro-tile. M staged TRANSPOSED (sMt[k][col])
// so B-operand reads are one conflict-free LDS.128 across lanes; A read as
// float4 along k. 8 LDS.128 per 64 FMA (was 32 LDS.32).
#define SXS 68   // row stride (floats): 16B-aligned, offsets row-groups by 16 banks
__global__ void gemm_kernel(const float* __restrict__ x,
                            const float* __restrict__ M,
                            __half* __restrict__ out, int N) {
    __shared__ float sx[DD][SXS];
    __shared__ float sMt[DD][SXS];
    int t = threadIdx.x;
    int base = blockIdx.x * DD;

#pragma unroll
    for (int i = 0; i < 4; i++) {
        int v = t + 256 * i;          // float4 index in [0,1024)
        int r = v >> 4;
        int c4 = (v & 15) * 4;
        // M row r, cols c4..c4+3 -> transposed store
        float4 mv = *(const float4*)&M[r * DD + c4];
        sMt[c4][r] = mv.x; sMt[c4 + 1][r] = mv.y; sMt[c4 + 2][r] = mv.z; sMt[c4 + 3][r] = mv.w;
        // x tile (guard rows)
        float4 xv = make_float4(0.f, 0.f, 0.f, 0.f);
        if (base + r < N)
            xv = *(const float4*)&x[(size_t)(base + r) * DD + c4];
        *(float4*)&sx[r][c4] = xv;
    }
    __syncthreads();

    int tc = (t & 15) * 4;
    int tr = (t >> 4) * 4;
    float acc[4][4];
#pragma unroll
    for (int i = 0; i < 4; i++)
#pragma unroll
        for (int j = 0; j < 4; j++) acc[i][j] = 0.f;

#pragma unroll
    for (int k = 0; k < DD; k += 4) {
        float4 b0 = *(const float4*)&sMt[k][tc];
        float4 b1 = *(const float4*)&sMt[k + 1][tc];
        float4 b2 = *(const float4*)&sMt[k + 2][tc];
        float4 b3 = *(const float4*)&sMt[k + 3][tc];
#pragma unroll
        for (int i = 0; i < 4; i++) {
            float4 a = *(const float4*)&sx[tr + i][k];
            acc[i][0] += a.x * b0.x + a.y * b1.x + a.z * b2.x + a.w * b3.x;
            acc[i][1] += a.x * b0.y + a.y * b1.y + a.z * b2.y + a.w * b3.y;
            acc[i][2] += a.x * b0.z + a.y * b1.z + a.z * b2.z + a.w * b3.z;
            acc[i][3] += a.x * b0.w + a.y * b1.w + a.z * b2.w + a.w * b3.w;
        }
    }

#pragma unroll
    for (int i = 0; i < 4; i++) {
        int row = base + tr + i;
        if (row < N) {
            __half2 h0 = __floats2half2_rn(acc[i][0], acc[i][1]);
            __half2 h1 = __floats2half2_rn(acc[i][2], acc[i][3]);
            uint2 pack;
            pack.x = *(const unsigned*)&h0;
            pack.y = *(const unsigned*)&h1;
            *(uint2*)&out[(size_t)row * DD + tc] = pack;
        }
    }
}

// ---------------- aggregation core (fp16 gather, uniform-ldg indices) -----
__device__ __forceinline__ void agg_core_h(const __half* __restrict__ yh,
                                           int beg, int end, int lane,
                                           __half2& m01, __half2& m23) {
    const __half2 ninf = __float2half2_rn(-INFINITY);
    m01 = ninf; m23 = ninf;
    const char* Y = (const char*)yh;
    int half_id = lane >> 4;
    int qb = (lane & 15) * 8;
    int p = beg;
    for (; p + 8 <= end; p += 8) {         // 4 edges per half-warp
        int o0 = __ldg(&g_esrc[p     + half_id]);
        int o1 = __ldg(&g_esrc[p + 2 + half_id]);
        int o2 = __ldg(&g_esrc[p + 4 + half_id]);
        int o3 = __ldg(&g_esrc[p + 6 + half_id]);
        uint2 a = *(const uint2*)(Y + o0 + qb);
        uint2 c = *(const uint2*)(Y + o1 + qb);
        uint2 d = *(const uint2*)(Y + o2 + qb);
        uint2 e = *(const uint2*)(Y + o3 + qb);
        m01 = __hmax2(m01, __hmax2(__hmax2(*(__half2*)&a.x, *(__half2*)&c.x),
                                   __hmax2(*(__half2*)&d.x, *(__half2*)&e.x)));
        m23 = __hmax2(m23, __hmax2(__hmax2(*(__half2*)&a.y, *(__half2*)&c.y),
                                   __hmax2(*(__half2*)&d.y, *(__half2*)&e.y)));
    }
    if (p + 4 <= end) {                    // 2 edges per half-warp
        int o0 = __ldg(&g_esrc[p     + half_id]);
        int o1 = __ldg(&g_esrc[p + 2 + half_id]);
        uint2 a = *(const uint2*)(Y + o0 + qb);
        uint2 c = *(const uint2*)(Y + o1 + qb);
        m01 = __hmax2(m01, __hmax2(*(__half2*)&a.x, *(__half2*)&c.x));
        m23 = __hmax2(m23, __hmax2(*(__half2*)&a.y, *(__half2*)&c.y));
        p += 4;
    }
    for (; p < end; p++) {                 // tail: both halves duplicate
        int o = __ldg(&g_esrc[p]);
        uint2 a = *(const uint2*)(Y + o + qb);
        m01 = __hmax2(m01, *(__half2*)&a.x);
        m23 = __hmax2(m23, *(__half2*)&a.y);
    }
    unsigned u01 = *(unsigned*)&m01, u23 = *(unsigned*)&m23;
    unsigned o01 = __shfl_xor_sync(0xffffffffu, u01, 16);
    unsigned o23 = __shfl_xor_sync(0xffffffffu, u23, 16);
    m01 = __hmax2(m01, *(__half2*)&o01);
    m23 = __hmax2(m23, *(__half2*)&o23);
}

// agg[i] = max_{src} yh[src] - yh[i]  (0 for isolated nodes)
__global__ void agg_kernel(const __half* __restrict__ yh,
                           float* __restrict__ out, int N) {
    int wid = (blockIdx.x * blockDim.x + threadIdx.x) >> 5;
    int lane = threadIdx.x & 31;
    if (wid >= N) return;
    int beg = g_rowptr[wid];
    int end = g_rowptr[wid + 1];
    __half2 m01, m23;
    agg_core_h(yh, beg, end, lane, m01, m23);
    if (lane < 16) {
        int q = lane;
        float4 o;
        if (beg == end) {
            o = make_float4(0.f, 0.f, 0.f, 0.f);
        } else {
            uint2 sp = *(const uint2*)&yh[(size_t)wid * DD + q * 4];
            float2 f01 = __half22float2(m01);
            float2 f23 = __half22float2(m23);
            float2 s01 = __half22float2(*(__half2*)&sp.x);
            float2 s23 = __half22float2(*(__half2*)&sp.y);
            o.x = f01.x - s01.x; o.y = f01.y - s01.y;
            o.z = f23.x - s23.x; o.w = f23.y - s23.y;
        }
        *(float4*)&out[(size_t)wid * DD + q * 4] = o;
    }
}

// last layer: agg + dot with folded head vector + sigmoid, fused.
__global__ void agg_final_kernel(const __half* __restrict__ yh,
                                 float* __restrict__ out, int N) {
    int wid = (blockIdx.x * blockDim.x + threadIdx.x) >> 5;
    int lane = threadIdx.x & 31;
    if (wid >= N) return;
    int beg = g_rowptr[wid];
    int end = g_rowptr[wid + 1];
    __half2 m01, m23;
    agg_core_h(yh, beg, end, lane, m01, m23);
    int q = lane & 15;
    float p = 0.f;
    if (beg != end) {
        uint2 sp = *(const uint2*)&yh[(size_t)wid * DD + q * 4];
        float2 f01 = __half22float2(m01);
        float2 f23 = __half22float2(m23);
        float2 s01 = __half22float2(*(__half2*)&sp.x);
        float2 s23 = __half22float2(*(__half2*)&sp.y);
        float4 vv = *(const float4*)&g_v[q * 4];
        p = (f01.x - s01.x) * vv.x + (f01.y - s01.y) * vv.y
          + (f23.x - s23.x) * vv.z + (f23.y - s23.y) * vv.w;
    }
#pragma unroll
    for (int off = 8; off; off >>= 1)
        p += __shfl_xor_sync(0xffffffffu, p, off);
    if (lane == 0)
        out[wid] = 1.f / (1.f + expf(-(p + g_bias)));
}

extern "C" void kernel_launch(void* const* d_in, const int* in_sizes, int n_in,
                              void* d_out, int out_size) {
    const float* x     = (const float*)d_in[0];
    const void*  edges = d_in[1];
    const float* Wp    = (const float*)d_in[2];
    const float* Wt    = (const float*)d_in[3];
    const float* Wout  = (const float*)d_in[4];
    const float* bout  = (const float*)d_in[5];
    float* out = (float*)d_out;

    int N = in_sizes[0] / DD;
    int E = in_sizes[1] / 2;

    __half* yhp;
    float *aggp, *m1p, *m2p;
    cudaGetSymbolAddress((void**)&yhp, g_yh);
    cudaGetSymbolAddress((void**)&aggp, g_agg);
    cudaGetSymbolAddress((void**)&m1p, g_M1);
    cudaGetSymbolAddress((void**)&m2p, g_M2);

    const int TB = 256;
    int ebl = (E + TB - 1) / TB;
    int wbl = ((N * 32) + TB - 1) / TB;   // warp-per-node grids
    int gbl = (N + DD - 1) / DD;          // 64-row GEMM tiles

    detect_kernel<<<1, 256>>>(edges);
    hist_kernel<<<ebl, TB>>>(edges, E);
    scan_fused<<<SCB, 256>>>(Wp, Wt, Wout, bout, N);
    scatter_kernel<<<ebl, TB>>>(edges, E);

    // layer 0
    gemm_kernel<<<gbl, 256>>>(x, Wp, yhp, N);
    agg_kernel<<<wbl, TB>>>(yhp, aggp, N);
    // layer 1
    gemm_kernel<<<gbl, 256>>>(aggp, m1p, yhp, N);
    agg_kernel<<<wbl, TB>>>(yhp, aggp, N);
    // layer 2 + head
    gemm_kernel<<<gbl, 256>>>(aggp, m2p, yhp, N);
    agg_final_kernel<<<wbl, TB>>>(yhp, out, N);
}

// round 9
// speedup vs baseline: 1.2904x; 1.0214x over previous
#include <cuda_runtime.h>
#include <cuda_fp16.h>
#include <math.h>
#include <stdint.h>

#define NMAX 100000
#define EMAX 1600000
#define DD 64
#define SCB 200          // scan blocks; 200*512 = 102400 >= NMAX; co-resident

typedef unsigned long long u64;

// ---------------- device scratch (no allocations allowed) ----------------
__device__ int    g_counts[NMAX];        // zeroed by scan_fused after use
__device__ int    g_fill[NMAX];
__device__ int    g_rowptr[NMAX + 1];
__device__ int    g_esrc[EMAX];          // BYTE offsets: src * 128
__device__ int    g_bsum[SCB];
__device__ unsigned long long g_barctr;  // monotonic, never reset (replay-safe)
__device__ __half g_yh[(size_t)NMAX * DD];
__device__ float  g_agg[(size_t)NMAX * DD];
__device__ float  g_M1[DD * DD];
__device__ float  g_M2[DD * DD];
__device__ float  g_v[DD];
__device__ float  g_bias;

// inline edge-dtype detect: warp 0 ballots 32 odd words (int64 => all zero;
// int32 dst values in [0,100000) => P[all 32 zero] ~ 1e-160). 256B L2-hot.
__device__ __forceinline__ int detect_is64_block(const void* edges, int* s64) {
    if (threadIdx.x < 32) {
        const int* w = (const int*)edges;
        int v = w[2 * threadIdx.x + 1];
        unsigned nz = __ballot_sync(0xffffffffu, v != 0);
        if (threadIdx.x == 0) *s64 = (nz == 0u) ? 1 : 0;
    }
    __syncthreads();
    return *s64;
}

__global__ void hist_kernel(const void* __restrict__ edges, int E) {
    __shared__ int s64;
    int is64 = detect_is64_block(edges, &s64);
    int e = blockIdx.x * blockDim.x + threadIdx.x;
    if (e >= E) return;
    int dst;
    if (is64) dst = (int)((const long long*)edges)[E + e];
    else      dst = ((const int*)edges)[E + e];
    atomicAdd(&g_counts[dst], 1);
}

// ---------------- fused: matprep + single-kernel scan ---------------------
__device__ __forceinline__ void grid_barrier_200() {
    __syncthreads();
    if (threadIdx.x == 0) {
        __threadfence();
        unsigned long long my = atomicAdd(&g_barctr, 1ULL) + 1ULL;
        unsigned long long target = ((my + SCB - 1) / SCB) * (unsigned long long)SCB;
        while (atomicAdd(&g_barctr, 0ULL) < target) { }
        __threadfence();
    }
    __syncthreads();
}

__global__ void scan_fused(const float* __restrict__ Wp,
                           const float* __restrict__ Wt,
                           const float* __restrict__ Wout,
                           const float* __restrict__ bout, int N) {
    int b = blockIdx.x, t = threadIdx.x;

    // ---- matprep on blocks 0..15 (4096 lanes) ----
    if (b < 16) {
        int id = b * 256 + t;
        int i = id >> 6, k = id & 63;
        float s1 = 0.f, s2 = 0.f;
#pragma unroll
        for (int m = 0; m < DD; m++) {
            s1 += Wp[1 * DD * DD + i * DD + m] * Wt[0 * DD * DD + m * DD + k];
            s2 += Wp[2 * DD * DD + i * DD + m] * Wt[1 * DD * DD + m * DD + k];
        }
        g_M1[id] = s1;
        g_M2[id] = s2;
        if (i == 0) {
            float sv = 0.f;
#pragma unroll
            for (int m = 0; m < DD; m++)
                sv += Wout[m] * Wt[2 * DD * DD + m * DD + k];
            g_v[k] = sv;
        }
        if (id == 0) g_bias = bout[0];
    }

    // ---- phase 1: block sum over its 512-element chunk ----
    __shared__ int sm[256];
    int base = b * 512 + t * 2;
    int c0 = (base < N) ? g_counts[base] : 0;
    int c1 = (base + 1 < N) ? g_counts[base + 1] : 0;
    int s = c0 + c1;
    sm[t] = s;
    __syncthreads();
    for (int off = 128; off; off >>= 1) {
        if (t < off) sm[t] += sm[t + off];
        __syncthreads();
    }
    if (t == 0) g_bsum[b] = sm[0];

    grid_barrier_200();

    // ---- phase 2a: block offset = exclusive prefix of g_bsum ----
    __shared__ int sb[256];
    sb[t] = (t < SCB) ? g_bsum[t] : 0;
    __syncthreads();
    for (int off = 1; off < 256; off <<= 1) {
        int v = (t >= off) ? sb[t - off] : 0;
        __syncthreads();
        sb[t] += v;
        __syncthreads();
    }
    int blockoff = (b == 0) ? 0 : sb[b - 1];
    if (b == SCB - 1 && t == 0) g_rowptr[N] = sb[SCB - 1];

    // ---- phase 2b: local exclusive scan + write + zero counts ----
    sm[t] = s;
    __syncthreads();
    for (int off = 1; off < 256; off <<= 1) {
        int v = (t >= off) ? sm[t - off] : 0;
        __syncthreads();
        sm[t] += v;
        __syncthreads();
    }
    int pre = sm[t] - s + blockoff;
    if (base < N)     { g_rowptr[base] = pre;          g_fill[base] = pre;          g_counts[base] = 0; }
    if (base + 1 < N) { g_rowptr[base + 1] = pre + c0; g_fill[base + 1] = pre + c0; g_counts[base + 1] = 0; }
}

__global__ void scatter_kernel(const void* __restrict__ edges, int E) {
    __shared__ int s64;
    int is64 = detect_is64_block(edges, &s64);
    int e = blockIdx.x * blockDim.x + threadIdx.x;
    if (e >= E) return;
    int src, dst;
    if (is64) {
        const long long* p = (const long long*)edges;
        src = (int)p[e]; dst = (int)p[E + e];
    } else {
        const int* p = (const int*)edges;
        src = p[e]; dst = p[E + e];
    }
    int pos = atomicAdd(&g_fill[dst], 1);
    g_esrc[pos] = src << 7;              // byte offset into fp16 rows (64*2B)
}

// ---------------- GEMM: yh = half( in @ M^T ), FFMA2 inner loop ----------
// 256 threads, 64x64 tile, 4x4 micro-tile. M staged TRANSPOSED (sMt[k][col]).
// Accumulators packed as f32x2; B pairs loaded as 64-bit from SMEM; A scalar
// duplicated via mov.b64 (ALU pipe, overlaps FMA pipe).
#define SXS 68   // row stride (floats)
__global__ void gemm_kernel(const float* __restrict__ x,
                            const float* __restrict__ M,
                            __half* __restrict__ out, int N) {
    __shared__ float sx[DD][SXS];
    __shared__ float sMt[DD][SXS];
    int t = threadIdx.x;
    int base = blockIdx.x * DD;

#pragma unroll
    for (int i = 0; i < 4; i++) {
        int v = t + 256 * i;          // float4 index in [0,1024)
        int r = v >> 4;
        int c4 = (v & 15) * 4;
        float4 mv = *(const float4*)&M[r * DD + c4];
        sMt[c4][r] = mv.x; sMt[c4 + 1][r] = mv.y; sMt[c4 + 2][r] = mv.z; sMt[c4 + 3][r] = mv.w;
        float4 xv = make_float4(0.f, 0.f, 0.f, 0.f);
        if (base + r < N)
            xv = *(const float4*)&x[(size_t)(base + r) * DD + c4];
        *(float4*)&sx[r][c4] = xv;
    }
    __syncthreads();

    int tc = (t & 15) * 4;
    int tr = (t >> 4) * 4;
    u64 acc2[4][2];                   // [row][col-pair]: (c,c+1) packed f32x2
#pragma unroll
    for (int i = 0; i < 4; i++) { acc2[i][0] = 0ULL; acc2[i][1] = 0ULL; }

#pragma unroll
    for (int k = 0; k < DD; k += 4) {
        // B pairs for the 4 k-values: each row k+j gives (b[tc],b[tc+1]),(b[tc+2],b[tc+3])
        u64 b0lo = *(const u64*)&sMt[k    ][tc], b0hi = *(const u64*)&sMt[k    ][tc + 2];
        u64 b1lo = *(const u64*)&sMt[k + 1][tc], b1hi = *(const u64*)&sMt[k + 1][tc + 2];
        u64 b2lo = *(const u64*)&sMt[k + 2][tc], b2hi = *(const u64*)&sMt[k + 2][tc + 2];
        u64 b3lo = *(const u64*)&sMt[k + 3][tc], b3hi = *(const u64*)&sMt[k + 3][tc + 2];
#pragma unroll
        for (int i = 0; i < 4; i++) {
            float4 a = *(const float4*)&sx[tr + i][k];
            u64 aa;
            asm("mov.b64 %0, {%1, %1};" : "=l"(aa) : "f"(a.x));
            asm("fma.rn.f32x2 %0, %1, %2, %0;" : "+l"(acc2[i][0]) : "l"(aa), "l"(b0lo));
            asm("fma.rn.f32x2 %0, %1, %2, %0;" : "+l"(acc2[i][1]) : "l"(aa), "l"(b0hi));
            asm("mov.b64 %0, {%1, %1};" : "=l"(aa) : "f"(a.y));
            asm("fma.rn.f32x2 %0, %1, %2, %0;" : "+l"(acc2[i][0]) : "l"(aa), "l"(b1lo));
            asm("fma.rn.f32x2 %0, %1, %2, %0;" : "+l"(acc2[i][1]) : "l"(aa), "l"(b1hi));
            asm("mov.b64 %0, {%1, %1};" : "=l"(aa) : "f"(a.z));
            asm("fma.rn.f32x2 %0, %1, %2, %0;" : "+l"(acc2[i][0]) : "l"(aa), "l"(b2lo));
            asm("fma.rn.f32x2 %0, %1, %2, %0;" : "+l"(acc2[i][1]) : "l"(aa), "l"(b2hi));
            asm("mov.b64 %0, {%1, %1};" : "=l"(aa) : "f"(a.w));
            asm("fma.rn.f32x2 %0, %1, %2, %0;" : "+l"(acc2[i][0]) : "l"(aa), "l"(b3lo));
            asm("fma.rn.f32x2 %0, %1, %2, %0;" : "+l"(acc2[i][1]) : "l"(aa), "l"(b3hi));
        }
    }

#pragma unroll
    for (int i = 0; i < 4; i++) {
        int row = base + tr + i;
        if (row < N) {
            float a0, a1, a2, a3;
            asm("mov.b64 {%0, %1}, %2;" : "=f"(a0), "=f"(a1) : "l"(acc2[i][0]));
            asm("mov.b64 {%0, %1}, %2;" : "=f"(a2), "=f"(a3) : "l"(acc2[i][1]));
            __half2 h0 = __floats2half2_rn(a0, a1);
            __half2 h1 = __floats2half2_rn(a2, a3);
            uint2 pack;
            pack.x = *(const unsigned*)&h0;
            pack.y = *(const unsigned*)&h1;
            *(uint2*)&out[(size_t)row * DD + tc] = pack;
        }
    }
}

// ---------------- aggregation core (fp16 gather, uniform-ldg indices) -----
__device__ __forceinline__ void agg_core_h(const __half* __restrict__ yh,
                                           int beg, int end, int lane,
                                           __half2& m01, __half2& m23) {
    const __half2 ninf = __float2half2_rn(-INFINITY);
    m01 = ninf; m23 = ninf;
    const char* Y = (const char*)yh;
    int half_id = lane >> 4;
    int qb = (lane & 15) * 8;
    int p = beg;
    for (; p + 8 <= end; p += 8) {         // 4 edges per half-warp
        int o0 = __ldg(&g_esrc[p     + half_id]);
        int o1 = __ldg(&g_esrc[p + 2 + half_id]);
        int o2 = __ldg(&g_esrc[p + 4 + half_id]);
        int o3 = __ldg(&g_esrc[p + 6 + half_id]);
        uint2 a = *(const uint2*)(Y + o0 + qb);
        uint2 c = *(const uint2*)(Y + o1 + qb);
        uint2 d = *(const uint2*)(Y + o2 + qb);
        uint2 e = *(const uint2*)(Y + o3 + qb);
        m01 = __hmax2(m01, __hmax2(__hmax2(*(__half2*)&a.x, *(__half2*)&c.x),
                                   __hmax2(*(__half2*)&d.x, *(__half2*)&e.x)));
        m23 = __hmax2(m23, __hmax2(__hmax2(*(__half2*)&a.y, *(__half2*)&c.y),
                                   __hmax2(*(__half2*)&d.y, *(__half2*)&e.y)));
    }
    if (p + 4 <= end) {                    // 2 edges per half-warp
        int o0 = __ldg(&g_esrc[p     + half_id]);
        int o1 = __ldg(&g_esrc[p + 2 + half_id]);
        uint2 a = *(const uint2*)(Y + o0 + qb);
        uint2 c = *(const uint2*)(Y + o1 + qb);
        m01 = __hmax2(m01, __hmax2(*(__half2*)&a.x, *(__half2*)&c.x));
        m23 = __hmax2(m23, __hmax2(*(__half2*)&a.y, *(__half2*)&c.y));
        p += 4;
    }
    for (; p < end; p++) {                 // tail: both halves duplicate
        int o = __ldg(&g_esrc[p]);
        uint2 a = *(const uint2*)(Y + o + qb);
        m01 = __hmax2(m01, *(__half2*)&a.x);
        m23 = __hmax2(m23, *(__half2*)&a.y);
    }
    unsigned u01 = *(unsigned*)&m01, u23 = *(unsigned*)&m23;
    unsigned o01 = __shfl_xor_sync(0xffffffffu, u01, 16);
    unsigned o23 = __shfl_xor_sync(0xffffffffu, u23, 16);
    m01 = __hmax2(m01, *(__half2*)&o01);
    m23 = __hmax2(m23, *(__half2*)&o23);
}

// agg[i] = max_{src} yh[src] - yh[i]  (0 for isolated nodes)
__global__ void agg_kernel(const __half* __restrict__ yh,
                           float* __restrict__ out, int N) {
    int wid = (blockIdx.x * blockDim.x + threadIdx.x) >> 5;
    int lane = threadIdx.x & 31;
    if (wid >= N) return;
    int beg = g_rowptr[wid];
    int end = g_rowptr[wid + 1];
    __half2 m01, m23;
    agg_core_h(yh, beg, end, lane, m01, m23);
    if (lane < 16) {
        int q = lane;
        float4 o;
        if (beg == end) {
            o = make_float4(0.f, 0.f, 0.f, 0.f);
        } else {
            uint2 sp = *(const uint2*)&yh[(size_t)wid * DD + q * 4];
            float2 f01 = __half22float2(m01);
            float2 f23 = __half22float2(m23);
            float2 s01 = __half22float2(*(__half2*)&sp.x);
            float2 s23 = __half22float2(*(__half2*)&sp.y);
            o.x = f01.x - s01.x; o.y = f01.y - s01.y;
            o.z = f23.x - s23.x; o.w = f23.y - s23.y;
        }
        *(float4*)&out[(size_t)wid * DD + q * 4] = o;
    }
}

// last layer: agg + dot with folded head vector + sigmoid, fused.
__global__ void agg_final_kernel(const __half* __restrict__ yh,
                                 float* __restrict__ out, int N) {
    int wid = (blockIdx.x * blockDim.x + threadIdx.x) >> 5;
    int lane = threadIdx.x & 31;
    if (wid >= N) return;
    int beg = g_rowptr[wid];
    int end = g_rowptr[wid + 1];
    __half2 m01, m23;
    agg_core_h(yh, beg, end, lane, m01, m23);
    int q = lane & 15;
    float p = 0.f;
    if (beg != end) {
        uint2 sp = *(const uint2*)&yh[(size_t)wid * DD + q * 4];
        float2 f01 = __half22float2(m01);
        float2 f23 = __half22float2(m23);
        float2 s01 = __half22float2(*(__half2*)&sp.x);
        float2 s23 = __half22float2(*(__half2*)&sp.y);
        float4 vv = *(const float4*)&g_v[q * 4];
        p = (f01.x - s01.x) * vv.x + (f01.y - s01.y) * vv.y
          + (f23.x - s23.x) * vv.z + (f23.y - s23.y) * vv.w;
    }
#pragma unroll
    for (int off = 8; off; off >>= 1)
        p += __shfl_xor_sync(0xffffffffu, p, off);
    if (lane == 0)
        out[wid] = 1.f / (1.f + expf(-(p + g_bias)));
}

extern "C" void kernel_launch(void* const* d_in, const int* in_sizes, int n_in,
                              void* d_out, int out_size) {
    const float* x     = (const float*)d_in[0];
    const void*  edges = d_in[1];
    const float* Wp    = (const float*)d_in[2];
    const float* Wt    = (const float*)d_in[3];
    const float* Wout  = (const float*)d_in[4];
    const float* bout  = (const float*)d_in[5];
    float* out = (float*)d_out;

    int N = in_sizes[0] / DD;
    int E = in_sizes[1] / 2;

    __half* yhp;
    float *aggp, *m1p, *m2p;
    cudaGetSymbolAddress((void**)&yhp, g_yh);
    cudaGetSymbolAddress((void**)&aggp, g_agg);
    cudaGetSymbolAddress((void**)&m1p, g_M1);
    cudaGetSymbolAddress((void**)&m2p, g_M2);

    const int TB = 256;
    int ebl = (E + TB - 1) / TB;
    int wbl = ((N * 32) + TB - 1) / TB;   // warp-per-node grids
    int gbl = (N + DD - 1) / DD;          // 64-row GEMM tiles

    hist_kernel<<<ebl, TB>>>(edges, E);
    scan_fused<<<SCB, 256>>>(Wp, Wt, Wout, bout, N);
    scatter_kernel<<<ebl, TB>>>(edges, E);

    // layer 0
    gemm_kernel<<<gbl, 256>>>(x, Wp, yhp, N);
    agg_kernel<<<wbl, TB>>>(yhp, aggp, N);
    // layer 1
    gemm_kernel<<<gbl, 256>>>(aggp, m1p, yhp, N);
    agg_kernel<<<wbl, TB>>>(yhp, aggp, N);
    // layer 2 + head
    gemm_kernel<<<gbl, 256>>>(aggp, m2p, yhp, N);
    agg_final_kernel<<<wbl, TB>>>(yhp, out, N);
}